// round 1
// baseline (speedup 1.0000x reference)
#include <cuda_runtime.h>

#define N_ATOMS 100000
#define N_PAIRS 3200000

// Scratch (no allocation allowed): per-atom {Z^|a_exp|, (float)Z} and folded params.
__device__ float2 g_atom[N_ATOMS];
__device__ float  g_params[12];

__global__ void __launch_bounds__(256) prep_kernel(
    const int* __restrict__ Z,
    const float* __restrict__ a_coef, const float* __restrict__ a_exp,
    const float* __restrict__ phi_c,  const float* __restrict__ phi_e,
    const float* __restrict__ ke,     const float* __restrict__ d2A,
    const float* __restrict__ e2m,
    float* __restrict__ out)
{
    int n = blockIdx.x * blockDim.x + threadIdx.x;
    if (n == 0) {
        float s = fabsf(phi_c[0]) + fabsf(phi_c[1]) + fabsf(phi_c[2]) + fabsf(phi_c[3]);
        float inv_s = 1.0f / s;
        #pragma unroll
        for (int k = 0; k < 4; k++) {
            g_params[k]     = fabsf(phi_c[k]) * inv_s;
            g_params[4 + k] = fabsf(phi_e[k]);
        }
        g_params[8] = 1.0f / fabsf(a_coef[0]);          // 1/|a_coefficient|
        g_params[9] = ke[0] * e2m[0] / d2A[0];          // folded prefactor K
    }
    if (n < N_ATOMS) {
        float zf = (float)Z[n];
        float za = __powf(zf, fabsf(a_exp[0]));          // Z^|a_exponent|
        g_atom[n] = make_float2(za, zf);
        out[n] = 0.0f;                                   // d_out is poisoned -> zero it
    }
}

__global__ void __launch_bounds__(256) pair_kernel(
    const float* __restrict__ dist, const float* __restrict__ cut,
    const int* __restrict__ idx_i,  const int* __restrict__ idx_j,
    float* __restrict__ out)
{
    int p = blockIdx.x * blockDim.x + threadIdx.x;

    // Broadcast params (uniform address -> single cached load per warp)
    float c0 = g_params[0], c1 = g_params[1], c2 = g_params[2], c3 = g_params[3];
    float e0 = g_params[4], e1 = g_params[5], e2 = g_params[6], e3 = g_params[7];
    float inv_a = g_params[8], K = g_params[9];

    float v = 0.0f;
    int seg = -1;
    if (p < N_PAIRS) {
        seg = idx_i[p];
        int j = idx_j[p];
        float2 ai = g_atom[seg];      // {za_i, Z_i} — near-sequential (idx_i sorted)
        float2 aj = g_atom[j];        // random gather, L2-resident (800 KB table)
        float  d  = dist[p];
        float  arg = d * (ai.x + aj.x) * inv_a;  // distances in model units (faithful)
        float phi = c0 * __expf(-e0 * arg)
                  + c1 * __expf(-e1 * arg)
                  + c2 * __expf(-e2 * arg)
                  + c3 * __expf(-e3 * arg);
        v = K * ai.y * aj.y * phi * cut[p] * __fdividef(1.0f, d);
    }

    // Warp segmented reduction over sorted idx_i: lanes with equal seg combine,
    // only the last lane of each run issues the atomic.
    const unsigned m = 0xffffffffu;
    int lane = threadIdx.x & 31;
    #pragma unroll
    for (int off = 1; off < 32; off <<= 1) {
        float v2 = __shfl_up_sync(m, v, off);
        int   s2 = __shfl_up_sync(m, seg, off);
        if (lane >= off && s2 == seg) v += v2;
    }
    int nseg = __shfl_down_sync(m, seg, 1);
    if (seg >= 0 && (lane == 31 || nseg != seg)) {
        atomicAdd(&out[seg], v);
    }
}

extern "C" void kernel_launch(void* const* d_in, const int* in_sizes, int n_in,
                              void* d_out, int out_size)
{
    const int*   Z    = (const int*)  d_in[0];
    const float* dist = (const float*)d_in[1];
    const float* cutv = (const float*)d_in[2];
    const int*   ii   = (const int*)  d_in[3];
    const int*   jj   = (const int*)  d_in[4];
    const float* ac   = (const float*)d_in[5];
    const float* ae   = (const float*)d_in[6];
    const float* pc   = (const float*)d_in[7];
    const float* pe   = (const float*)d_in[8];
    const float* ke   = (const float*)d_in[9];
    const float* d2A  = (const float*)d_in[10];
    const float* e2m  = (const float*)d_in[11];
    float* out = (float*)d_out;

    prep_kernel<<<(N_ATOMS + 255) / 256, 256>>>(Z, ac, ae, pc, pe, ke, d2A, e2m, out);
    pair_kernel<<<(N_PAIRS + 255) / 256, 256>>>(dist, cutv, ii, jj, out);
}

// round 2
// speedup vs baseline: 1.2073x; 1.2073x over previous
#include <cuda_runtime.h>

#define N_ATOMS 100000
#define N_PAIRS 3200000
#define NT4     (N_PAIRS / 4)   // 800000, exact

// Scratch (no allocation allowed)
__device__ float2 g_atom[N_ATOMS];     // {Z^|a_exp|, (float)Z}
__device__ float4 g_params4[3];        // [0]=c0..c3  [1]=e0..e3  [2]={inv_a, K, 0, 0}

__global__ void __launch_bounds__(256) prep_kernel(
    const int* __restrict__ Z,
    const float* __restrict__ a_coef, const float* __restrict__ a_exp,
    const float* __restrict__ phi_c,  const float* __restrict__ phi_e,
    const float* __restrict__ ke,     const float* __restrict__ d2A,
    const float* __restrict__ e2m,
    float* __restrict__ out)
{
    int n = blockIdx.x * blockDim.x + threadIdx.x;
    if (n == 0) {
        float a0 = fabsf(phi_c[0]), a1 = fabsf(phi_c[1]),
              a2 = fabsf(phi_c[2]), a3 = fabsf(phi_c[3]);
        float inv_s = 1.0f / (a0 + a1 + a2 + a3);
        g_params4[0] = make_float4(a0 * inv_s, a1 * inv_s, a2 * inv_s, a3 * inv_s);
        g_params4[1] = make_float4(fabsf(phi_e[0]), fabsf(phi_e[1]),
                                   fabsf(phi_e[2]), fabsf(phi_e[3]));
        g_params4[2] = make_float4(1.0f / fabsf(a_coef[0]),
                                   ke[0] * e2m[0] / d2A[0], 0.0f, 0.0f);
    }
    if (n < N_ATOMS) {
        float zf = (float)Z[n];
        float za = __powf(zf, fabsf(a_exp[0]));
        g_atom[n] = make_float2(za, zf);
        out[n] = 0.0f;                     // d_out is poisoned -> zero it
    }
}

__device__ __forceinline__ float pair_val(
    float d, float ct, float2 ai, float2 aj,
    float4 C, float4 E, float inv_a, float K)
{
    float arg = d * (ai.x + aj.x) * inv_a;
    float phi = C.x * __expf(-E.x * arg)
              + C.y * __expf(-E.y * arg)
              + C.z * __expf(-E.z * arg)
              + C.w * __expf(-E.w * arg);
    return K * ai.y * aj.y * phi * ct * __fdividef(1.0f, d);
}

__global__ void __launch_bounds__(256) pair_kernel(
    const float4* __restrict__ dist, const float4* __restrict__ cut,
    const int4*  __restrict__ idx_i, const int4*  __restrict__ idx_j,
    float* __restrict__ out)
{
    int t = blockIdx.x * blockDim.x + threadIdx.x;   // t < NT4, no tail
    const unsigned m = 0xffffffffu;
    int lane = threadIdx.x & 31;

    float4 C  = g_params4[0];
    float4 E  = g_params4[1];
    float4 P2 = g_params4[2];
    float inv_a = P2.x, K = P2.y;

    int4   si = idx_i[t];
    int4   sj = idx_j[t];
    float4 d  = dist[t];
    float4 ct = cut[t];

    // gathers: si.* are nearly identical (sorted) -> L1 hits; sj.* random, L2
    float2 ai0 = g_atom[si.x], ai1 = g_atom[si.y], ai2 = g_atom[si.z], ai3 = g_atom[si.w];
    float2 aj0 = g_atom[sj.x], aj1 = g_atom[sj.y], aj2 = g_atom[sj.z], aj3 = g_atom[sj.w];

    float v0 = pair_val(d.x, ct.x, ai0, aj0, C, E, inv_a, K);
    float v1 = pair_val(d.y, ct.y, ai1, aj1, C, E, inv_a, K);
    float v2 = pair_val(d.z, ct.z, ai2, aj2, C, E, inv_a, K);
    float v3 = pair_val(d.w, ct.w, ai3, aj3, C, E, inv_a, K);

    // In-thread serial segmented combine (idx_i sorted; boundaries are rare).
    int   seg = si.x;
    float acc = v0;
    if (si.y == seg) acc += v1; else { atomicAdd(&out[seg], acc); seg = si.y; acc = v1; }
    if (si.z == seg) acc += v2; else { atomicAdd(&out[seg], acc); seg = si.z; acc = v2; }
    if (si.w == seg) acc += v3; else { atomicAdd(&out[seg], acc); seg = si.w; acc = v3; }

    // Warp segmented inclusive scan over (seg, acc): ballot head-lane trick.
    int segp = __shfl_up_sync(m, seg, 1);
    bool head = (lane == 0) || (segp != seg);
    unsigned hb = __ballot_sync(m, head);
    unsigned mask_le = 0xffffffffu >> (31 - lane);
    int head_lane = 31 - __clz(hb & mask_le);
    #pragma unroll
    for (int off = 1; off < 32; off <<= 1) {
        float vv = __shfl_up_sync(m, acc, off);
        if (lane - off >= head_lane) acc += vv;
    }
    unsigned tails = (hb >> 1) | 0x80000000u;   // tail(k) = head(k+1) or k==31
    if ((tails >> lane) & 1) {
        atomicAdd(&out[seg], acc);
    }
}

extern "C" void kernel_launch(void* const* d_in, const int* in_sizes, int n_in,
                              void* d_out, int out_size)
{
    const int*   Z    = (const int*)  d_in[0];
    const float* dist = (const float*)d_in[1];
    const float* cutv = (const float*)d_in[2];
    const int*   ii   = (const int*)  d_in[3];
    const int*   jj   = (const int*)  d_in[4];
    const float* ac   = (const float*)d_in[5];
    const float* ae   = (const float*)d_in[6];
    const float* pc   = (const float*)d_in[7];
    const float* pe   = (const float*)d_in[8];
    const float* ke   = (const float*)d_in[9];
    const float* d2A  = (const float*)d_in[10];
    const float* e2m  = (const float*)d_in[11];
    float* out = (float*)d_out;

    prep_kernel<<<(N_ATOMS + 255) / 256, 256>>>(Z, ac, ae, pc, pe, ke, d2A, e2m, out);
    pair_kernel<<<(NT4 + 255) / 256, 256>>>(
        (const float4*)dist, (const float4*)cutv,
        (const int4*)ii, (const int4*)jj, out);
}

// round 3
// speedup vs baseline: 1.4804x; 1.2262x over previous
#include <cuda_runtime.h>

#define N_ATOMS 100000
#define N_PAIRS 3200000
#define NT4     (N_PAIRS / 4)   // 800000, exact
#define ZMAX    96

// Scratch (no allocation allowed)
__device__ unsigned char g_z8[N_ATOMS];   // atomic number, 1..94 (100KB — L1-resident)
__device__ float  g_zpow[ZMAX];           // z^|a_exponent| LUT
__device__ float4 g_params4[3];           // [0]=c0..c3  [1]=e0..e3  [2]={inv_a, K, 0, 0}

__global__ void __launch_bounds__(256) prep_kernel(
    const int* __restrict__ Z,
    const float* __restrict__ a_coef, const float* __restrict__ a_exp,
    const float* __restrict__ phi_c,  const float* __restrict__ phi_e,
    const float* __restrict__ ke,     const float* __restrict__ d2A,
    const float* __restrict__ e2m,
    float* __restrict__ out)
{
    int n = blockIdx.x * blockDim.x + threadIdx.x;
    if (n == 0) {
        float a0 = fabsf(phi_c[0]), a1 = fabsf(phi_c[1]),
              a2 = fabsf(phi_c[2]), a3 = fabsf(phi_c[3]);
        float inv_s = 1.0f / (a0 + a1 + a2 + a3);
        g_params4[0] = make_float4(a0 * inv_s, a1 * inv_s, a2 * inv_s, a3 * inv_s);
        g_params4[1] = make_float4(fabsf(phi_e[0]), fabsf(phi_e[1]),
                                   fabsf(phi_e[2]), fabsf(phi_e[3]));
        g_params4[2] = make_float4(1.0f / fabsf(a_coef[0]),
                                   ke[0] * e2m[0] / d2A[0], 0.0f, 0.0f);
    }
    if (n < ZMAX) {
        g_zpow[n] = __powf((float)n, fabsf(a_exp[0]));   // n=0 unused
    }
    if (n < N_ATOMS) {
        g_z8[n] = (unsigned char)Z[n];                    // Z in [1,95)
        out[n] = 0.0f;                                    // d_out poisoned -> zero it
    }
}

__device__ __forceinline__ float pair_val(
    float d, float ct, int zi, int zj, const float* __restrict__ s_zpow,
    float4 C, float4 E, float inv_a, float K)
{
    float za  = s_zpow[zi] + s_zpow[zj];
    float arg = d * za * inv_a;
    float phi = C.x * __expf(-E.x * arg)
              + C.y * __expf(-E.y * arg)
              + C.z * __expf(-E.z * arg)
              + C.w * __expf(-E.w * arg);
    float zz = (float)zi * (float)zj;
    return K * zz * phi * ct * __fdividef(1.0f, d);
}

__global__ void __launch_bounds__(256) pair_kernel(
    const float4* __restrict__ dist, const float4* __restrict__ cut,
    const int4*  __restrict__ idx_i, const int4*  __restrict__ idx_j,
    float* __restrict__ out)
{
    __shared__ float  s_zpow[ZMAX];
    __shared__ float4 s_par[3];
    int tid = threadIdx.x;
    if (tid < ZMAX) s_zpow[tid] = g_zpow[tid];
    if (tid < 3)    s_par[tid]  = g_params4[tid];
    __syncthreads();

    int t = blockIdx.x * blockDim.x + tid;    // t < NT4, exact grid
    const unsigned m = 0xffffffffu;
    int lane = tid & 31;

    float4 C  = s_par[0];
    float4 E  = s_par[1];
    float inv_a = s_par[2].x, K = s_par[2].y;

    int4   si = idx_i[t];
    int4   sj = idx_j[t];
    float4 d  = dist[t];
    float4 ct = cut[t];

    // 1-byte gathers into a 100KB table: L1-resident after warm lines.
    int zi0 = g_z8[si.x], zi1 = g_z8[si.y], zi2 = g_z8[si.z], zi3 = g_z8[si.w];
    int zj0 = g_z8[sj.x], zj1 = g_z8[sj.y], zj2 = g_z8[sj.z], zj3 = g_z8[sj.w];

    float v0 = pair_val(d.x, ct.x, zi0, zj0, s_zpow, C, E, inv_a, K);
    float v1 = pair_val(d.y, ct.y, zi1, zj1, s_zpow, C, E, inv_a, K);
    float v2 = pair_val(d.z, ct.z, zi2, zj2, s_zpow, C, E, inv_a, K);
    float v3 = pair_val(d.w, ct.w, zi3, zj3, s_zpow, C, E, inv_a, K);

    // In-thread serial segmented combine (idx_i sorted; boundaries rare).
    int   seg = si.x;
    float acc = v0;
    if (si.y == seg) acc += v1; else { atomicAdd(&out[seg], acc); seg = si.y; acc = v1; }
    if (si.z == seg) acc += v2; else { atomicAdd(&out[seg], acc); seg = si.z; acc = v2; }
    if (si.w == seg) acc += v3; else { atomicAdd(&out[seg], acc); seg = si.w; acc = v3; }

    // Warp segmented inclusive scan over (seg, acc).
    int segp = __shfl_up_sync(m, seg, 1);
    bool head = (lane == 0) || (segp != seg);
    unsigned hb = __ballot_sync(m, head);
    unsigned mask_le = 0xffffffffu >> (31 - lane);
    int head_lane = 31 - __clz(hb & mask_le);
    #pragma unroll
    for (int off = 1; off < 32; off <<= 1) {
        float vv = __shfl_up_sync(m, acc, off);
        if (lane - off >= head_lane) acc += vv;
    }
    unsigned tails = (hb >> 1) | 0x80000000u;   // tail(k) = head(k+1) or k==31
    if ((tails >> lane) & 1) {
        atomicAdd(&out[seg], acc);
    }
}

extern "C" void kernel_launch(void* const* d_in, const int* in_sizes, int n_in,
                              void* d_out, int out_size)
{
    const int*   Z    = (const int*)  d_in[0];
    const float* dist = (const float*)d_in[1];
    const float* cutv = (const float*)d_in[2];
    const int*   ii   = (const int*)  d_in[3];
    const int*   jj   = (const int*)  d_in[4];
    const float* ac   = (const float*)d_in[5];
    const float* ae   = (const float*)d_in[6];
    const float* pc   = (const float*)d_in[7];
    const float* pe   = (const float*)d_in[8];
    const float* ke   = (const float*)d_in[9];
    const float* d2A  = (const float*)d_in[10];
    const float* e2m  = (const float*)d_in[11];
    float* out = (float*)d_out;

    prep_kernel<<<(N_ATOMS + 255) / 256, 256>>>(Z, ac, ae, pc, pe, ke, d2A, e2m, out);
    pair_kernel<<<(NT4 + 255) / 256, 256>>>(
        (const float4*)dist, (const float4*)cutv,
        (const int4*)ii, (const int4*)jj, out);
}